// round 9
// baseline (speedup 1.0000x reference)
#include <cuda_runtime.h>
#include <stdint.h>

// Problem constants (fixed by the reference)
#define NXD 512
#define NYD 512
#define CH  128
#define BATCH 4
#define CELLS (NYD * NXD)               // 262144 cells per batch
#define TOTAL_CELLS (BATCH * CELLS)     // 1,048,576  (= 1<<20)
#define NQUADS (TOTAL_CELLS / 4)        // 262144 x-quads

// Scratch: per-cell pillar index, reset to -1 each call via a 0xFF memset node.
__device__ int g_idx[TOTAL_CELLS];
// Zero feature row for empty cells (zero-initialized, read-only -> hot in L2).
__device__ float4 g_zero_row[CH / 4];

// ---------------------------------------------------------------------------
// Pass 1: scatter pillar index into canvas. coords row = [b, z, y, x], NZ=1.
// ---------------------------------------------------------------------------
__global__ void build_idx_kernel(const int* __restrict__ coords, int P) {
    int p = blockIdx.x * blockDim.x + threadIdx.x;
    if (p >= P) return;
    int4 c = ((const int4*)coords)[p];               // b, z, y, x
    int cell = (c.x + c.y) * CELLS + c.z * NXD + c.w;
    g_idx[cell] = p;
}

// ---------------------------------------------------------------------------
// Pass 2: gather. Each thread owns 4 consecutive x-cells x 8 channels
// (one channel octet). Stores are STG.128: warp = 32 lane-quads = 512
// contiguous bytes per channel store (3 cyc/128B at the LSU vs 5 for
// scalar stores). Loads: 2 float4 per row x 4 rows, front-batched (MLP=8).
// Channel octet is the SLOW grid dimension so concurrently resident CTAs
// write the same channel regions (DRAM write locality).
// ---------------------------------------------------------------------------
__global__ __launch_bounds__(256) void gather_kernel(
    const float* __restrict__ feat, float* __restrict__ out)
{
    int T = blockIdx.x * blockDim.x + threadIdx.x;   // 16*NQUADS threads
    int o    = T >> 18;                              // channel octet 0..15
    int quad = T & (NQUADS - 1);                     // x-quad id
    int cell0 = quad << 2;

    int4 pq = __ldg((const int4*)g_idx + quad);      // 4 cell indices, 512B/warp

    const float4* zr = g_zero_row + o * 2;
    const float4* r0 = (pq.x >= 0) ? (const float4*)(feat + (size_t)pq.x * CH + o * 8) : zr;
    const float4* r1 = (pq.y >= 0) ? (const float4*)(feat + (size_t)pq.y * CH + o * 8) : zr;
    const float4* r2 = (pq.z >= 0) ? (const float4*)(feat + (size_t)pq.z * CH + o * 8) : zr;
    const float4* r3 = (pq.w >= 0) ? (const float4*)(feat + (size_t)pq.w * CH + o * 8) : zr;

    // Front-batch all 8 loads (8 channels = 32B per row, 2 float4 per row)
    float4 a0 = __ldg(r0 + 0); float4 a1 = __ldg(r0 + 1);
    float4 b0 = __ldg(r1 + 0); float4 b1 = __ldg(r1 + 1);
    float4 c0 = __ldg(r2 + 0); float4 c1 = __ldg(r2 + 1);
    float4 d0 = __ldg(r3 + 0); float4 d1 = __ldg(r3 + 1);

    int b  = cell0 >> 18;                            // batch
    int xy = cell0 & (CELLS - 1);                    // y*512 + x within batch
    // out[b][c][y][x], c = 8o + j; float4 store covers x..x+3
    float* ob = out + (size_t)(b * CH + o * 8) * CELLS + xy;

    *(float4*)(ob + (size_t)0 * CELLS) = make_float4(a0.x, b0.x, c0.x, d0.x);
    *(float4*)(ob + (size_t)1 * CELLS) = make_float4(a0.y, b0.y, c0.y, d0.y);
    *(float4*)(ob + (size_t)2 * CELLS) = make_float4(a0.z, b0.z, c0.z, d0.z);
    *(float4*)(ob + (size_t)3 * CELLS) = make_float4(a0.w, b0.w, c0.w, d0.w);
    *(float4*)(ob + (size_t)4 * CELLS) = make_float4(a1.x, b1.x, c1.x, d1.x);
    *(float4*)(ob + (size_t)5 * CELLS) = make_float4(a1.y, b1.y, c1.y, d1.y);
    *(float4*)(ob + (size_t)6 * CELLS) = make_float4(a1.z, b1.z, c1.z, d1.z);
    *(float4*)(ob + (size_t)7 * CELLS) = make_float4(a1.w, b1.w, c1.w, d1.w);
}

// ---------------------------------------------------------------------------
// Launch: identify inputs by size (batch_size scalar / features / coords).
// ---------------------------------------------------------------------------
extern "C" void kernel_launch(void* const* d_in, const int* in_sizes, int n_in,
                              void* d_out, int out_size)
{
    // features is the largest input (P*128 floats); coords has P*4 ints.
    int fi = 0;
    long long best = -1;
    for (int i = 0; i < n_in; ++i) {
        if ((long long)in_sizes[i] > best) { best = in_sizes[i]; fi = i; }
    }
    const float* feat = (const float*)d_in[fi];
    int P = in_sizes[fi] / CH;

    const int* coords = nullptr;
    for (int i = 0; i < n_in; ++i) {
        if (i != fi && in_sizes[i] == P * 4) { coords = (const int*)d_in[i]; break; }
    }
    if (!coords) { // fallback: second-largest input
        int ci = -1; long long b2 = -1;
        for (int i = 0; i < n_in; ++i)
            if (i != fi && (long long)in_sizes[i] > b2) { b2 = in_sizes[i]; ci = i; }
        coords = (const int*)d_in[ci];
    }

    float* out = (float*)d_out;

    // Pass 0: reset index canvas to -1 (0xFF bytes). Memset node: capturable,
    // no allocation, ~1us for 4 MiB.
    void* idx_ptr = nullptr;
    cudaGetSymbolAddress(&idx_ptr, g_idx);
    cudaMemsetAsync(idx_ptr, 0xFF, TOTAL_CELLS * sizeof(int), 0);

    // Pass 1: scatter pillar indices
    build_idx_kernel<<<(P + 255) / 256, 256>>>(coords, P);

    // Pass 2: gather + transpose (4 x-cells x 8 channels per thread)
    gather_kernel<<<(16 * NQUADS) / 256, 256>>>(feat, out);
}

// round 10
// speedup vs baseline: 1.0860x; 1.0860x over previous
#include <cuda_runtime.h>
#include <stdint.h>

// Problem constants (fixed by the reference)
#define NXD 512
#define NYD 512
#define CH  128
#define BATCH 4
#define CELLS (NYD * NXD)               // 262144 cells per batch
#define TOTAL_CELLS (BATCH * CELLS)     // 1,048,576  (= 1<<20)
#define NQUADS (TOTAL_CELLS / 4)        // 262144 x-quads
#define CH_STRIDE_F4 (CELLS / 4)        // 65536 float4 per channel plane

// Scratch: per-cell pillar index, reset to -1 each call via a 0xFF memset node.
__device__ int g_idx[TOTAL_CELLS];
// Zero feature row for empty cells (zero-initialized, read-only -> hot in L2).
__device__ float4 g_zero_row[CH / 4];

// ---------------------------------------------------------------------------
// Pass 1: scatter pillar index into canvas. coords row = [b, z, y, x], NZ=1.
// ---------------------------------------------------------------------------
__global__ void build_idx_kernel(const int* __restrict__ coords, int P) {
    int p = blockIdx.x * blockDim.x + threadIdx.x;
    if (p >= P) return;
    int4 c = ((const int4*)coords)[p];               // b, z, y, x
    int cell = (c.x + c.y) * CELLS + c.z * NXD + c.w;
    g_idx[cell] = p;
}

// ---------------------------------------------------------------------------
// Pass 2: gather. Each thread owns 4 consecutive x-cells x ALL 128 channels.
//  - Reads: full 512B feature rows per thread -> zero sector amplification.
//  - Stores: float4 across the 4 x-cells -> each warp store-op is 512
//    contiguous bytes in one channel plane (good DRAM page dwell; R9 measured
//    73% DRAM eff with this shape).
//  - Loop: 16 iterations of (8 front-batched LDG.128 -> reg transpose ->
//    8 STG.128 over channels 8k..8k+7). Keeps staging to 8 float4.
// ---------------------------------------------------------------------------
__global__ __launch_bounds__(128) void gather_kernel(
    const float* __restrict__ feat, float* __restrict__ out)
{
    int quad = blockIdx.x * blockDim.x + threadIdx.x;   // NQUADS threads
    if (quad >= NQUADS) return;
    int cell0 = quad << 2;

    int4 pq = __ldg((const int4*)g_idx + quad);      // 4 cell indices

    const float4* r0 = (pq.x >= 0) ? (const float4*)(feat + (size_t)pq.x * CH) : g_zero_row;
    const float4* r1 = (pq.y >= 0) ? (const float4*)(feat + (size_t)pq.y * CH) : g_zero_row;
    const float4* r2 = (pq.z >= 0) ? (const float4*)(feat + (size_t)pq.z * CH) : g_zero_row;
    const float4* r3 = (pq.w >= 0) ? (const float4*)(feat + (size_t)pq.w * CH) : g_zero_row;

    int b  = cell0 >> 18;                            // batch
    int xy = cell0 & (CELLS - 1);                    // y*512 + x within batch
    float4* ob = (float4*)out + (size_t)b * CH * CH_STRIDE_F4 + (xy >> 2);

    #pragma unroll 1
    for (int k = 0; k < 16; ++k) {                   // channels 8k .. 8k+7
        // Front-batch 8 loads (2 float4 per row x 4 rows)
        float4 a0 = __ldg(r0 + 2 * k); float4 a1 = __ldg(r0 + 2 * k + 1);
        float4 b0 = __ldg(r1 + 2 * k); float4 b1 = __ldg(r1 + 2 * k + 1);
        float4 c0 = __ldg(r2 + 2 * k); float4 c1 = __ldg(r2 + 2 * k + 1);
        float4 d0 = __ldg(r3 + 2 * k); float4 d1 = __ldg(r3 + 2 * k + 1);

        float4* o = ob + (size_t)(8 * k) * CH_STRIDE_F4;
        o[(size_t)0 * CH_STRIDE_F4] = make_float4(a0.x, b0.x, c0.x, d0.x);
        o[(size_t)1 * CH_STRIDE_F4] = make_float4(a0.y, b0.y, c0.y, d0.y);
        o[(size_t)2 * CH_STRIDE_F4] = make_float4(a0.z, b0.z, c0.z, d0.z);
        o[(size_t)3 * CH_STRIDE_F4] = make_float4(a0.w, b0.w, c0.w, d0.w);
        o[(size_t)4 * CH_STRIDE_F4] = make_float4(a1.x, b1.x, c1.x, d1.x);
        o[(size_t)5 * CH_STRIDE_F4] = make_float4(a1.y, b1.y, c1.y, d1.y);
        o[(size_t)6 * CH_STRIDE_F4] = make_float4(a1.z, b1.z, c1.z, d1.z);
        o[(size_t)7 * CH_STRIDE_F4] = make_float4(a1.w, b1.w, c1.w, d1.w);
    }
}

// ---------------------------------------------------------------------------
// Launch: identify inputs by size (batch_size scalar / features / coords).
// ---------------------------------------------------------------------------
extern "C" void kernel_launch(void* const* d_in, const int* in_sizes, int n_in,
                              void* d_out, int out_size)
{
    // features is the largest input (P*128 floats); coords has P*4 ints.
    int fi = 0;
    long long best = -1;
    for (int i = 0; i < n_in; ++i) {
        if ((long long)in_sizes[i] > best) { best = in_sizes[i]; fi = i; }
    }
    const float* feat = (const float*)d_in[fi];
    int P = in_sizes[fi] / CH;

    const int* coords = nullptr;
    for (int i = 0; i < n_in; ++i) {
        if (i != fi && in_sizes[i] == P * 4) { coords = (const int*)d_in[i]; break; }
    }
    if (!coords) { // fallback: second-largest input
        int ci = -1; long long b2 = -1;
        for (int i = 0; i < n_in; ++i)
            if (i != fi && (long long)in_sizes[i] > b2) { b2 = in_sizes[i]; ci = i; }
        coords = (const int*)d_in[ci];
    }

    float* out = (float*)d_out;

    // Pass 0: reset index canvas to -1 (0xFF bytes). Memset node: capturable,
    // no allocation, ~1us for 4 MiB.
    void* idx_ptr = nullptr;
    cudaGetSymbolAddress(&idx_ptr, g_idx);
    cudaMemsetAsync(idx_ptr, 0xFF, TOTAL_CELLS * sizeof(int), 0);

    // Pass 1: scatter pillar indices
    build_idx_kernel<<<(P + 255) / 256, 256>>>(coords, P);

    // Pass 2: gather + transpose (4 x-cells x 128 channels per thread)
    gather_kernel<<<NQUADS / 128, 128>>>(feat, out);
}

// round 11
// speedup vs baseline: 1.2406x; 1.1423x over previous
#include <cuda_runtime.h>
#include <stdint.h>

// Problem constants (fixed by the reference)
#define NXD 512
#define NYD 512
#define CH  128
#define BATCH 4
#define CELLS (NYD * NXD)               // 262144 cells per batch
#define TOTAL_CELLS (BATCH * CELLS)     // 1,048,576  (= 1<<20)
#define NQUADS (TOTAL_CELLS / 4)        // 262144 x-quads
#define CH_STRIDE_F4 (CELLS / 4)        // 65536 float4 per channel plane

// Scratch: per-cell pillar index, reset to -1 each call via a 0xFF memset node.
__device__ int g_idx[TOTAL_CELLS];
// Zero feature row for empty cells (zero-initialized, read-only -> hot in L2).
__device__ float4 g_zero_row[CH / 4];

// ---------------------------------------------------------------------------
// Pass 1: scatter pillar index into canvas. coords row = [b, z, y, x], NZ=1.
// ---------------------------------------------------------------------------
__global__ void build_idx_kernel(const int* __restrict__ coords, int P) {
    int p = blockIdx.x * blockDim.x + threadIdx.x;
    if (p >= P) return;
    int4 c = ((const int4*)coords)[p];               // b, z, y, x
    int cell = (c.x + c.y) * CELLS + c.z * NXD + c.w;
    g_idx[cell] = p;
}

// ---------------------------------------------------------------------------
// Pass 2: gather. FOUR threads per x-quad; each thread owns 4 consecutive
// x-cells x 32 channels (one quarter-row = exactly one 128B line per row ->
// zero read amplification). Quarter comes from the HIGH grid bits so
// consecutive threads are consecutive quads: every warp float4 store is 512
// contiguous bytes in one channel plane. 1M threads (R7-level concurrency)
// with only a 4-iteration serial chain per thread (R10 had 16).
// ---------------------------------------------------------------------------
__global__ __launch_bounds__(256) void gather_kernel(
    const float* __restrict__ feat, float* __restrict__ out)
{
    int T = blockIdx.x * blockDim.x + threadIdx.x;   // 4*NQUADS threads
    int q    = T >> 18;                              // channel quarter 0..3
    int quad = T & (NQUADS - 1);
    int cell0 = quad << 2;

    int4 pq = __ldg((const int4*)g_idx + quad);      // 4 cell indices

    const float4* zr = g_zero_row + q * 8;
    const float4* r0 = (pq.x >= 0) ? (const float4*)(feat + (size_t)pq.x * CH + q * 32) : zr;
    const float4* r1 = (pq.y >= 0) ? (const float4*)(feat + (size_t)pq.y * CH + q * 32) : zr;
    const float4* r2 = (pq.z >= 0) ? (const float4*)(feat + (size_t)pq.z * CH + q * 32) : zr;
    const float4* r3 = (pq.w >= 0) ? (const float4*)(feat + (size_t)pq.w * CH + q * 32) : zr;

    int b  = cell0 >> 18;                            // batch
    int xy = cell0 & (CELLS - 1);                    // y*512 + x within batch
    float4* ob = (float4*)out + ((size_t)b * CH + q * 32) * CH_STRIDE_F4 + (xy >> 2);

    #pragma unroll 1
    for (int k = 0; k < 4; ++k) {                    // channels q*32+8k .. +8k+7
        // Front-batch 8 loads (2 float4 per row x 4 rows; same 128B line per
        // row across the 4 iterations -> L1 hits after the first touch)
        float4 a0 = __ldg(r0 + 2 * k); float4 a1 = __ldg(r0 + 2 * k + 1);
        float4 b0 = __ldg(r1 + 2 * k); float4 b1 = __ldg(r1 + 2 * k + 1);
        float4 c0 = __ldg(r2 + 2 * k); float4 c1 = __ldg(r2 + 2 * k + 1);
        float4 d0 = __ldg(r3 + 2 * k); float4 d1 = __ldg(r3 + 2 * k + 1);

        float4* o = ob + (size_t)(8 * k) * CH_STRIDE_F4;
        o[(size_t)0 * CH_STRIDE_F4] = make_float4(a0.x, b0.x, c0.x, d0.x);
        o[(size_t)1 * CH_STRIDE_F4] = make_float4(a0.y, b0.y, c0.y, d0.y);
        o[(size_t)2 * CH_STRIDE_F4] = make_float4(a0.z, b0.z, c0.z, d0.z);
        o[(size_t)3 * CH_STRIDE_F4] = make_float4(a0.w, b0.w, c0.w, d0.w);
        o[(size_t)4 * CH_STRIDE_F4] = make_float4(a1.x, b1.x, c1.x, d1.x);
        o[(size_t)5 * CH_STRIDE_F4] = make_float4(a1.y, b1.y, c1.y, d1.y);
        o[(size_t)6 * CH_STRIDE_F4] = make_float4(a1.z, b1.z, c1.z, d1.z);
        o[(size_t)7 * CH_STRIDE_F4] = make_float4(a1.w, b1.w, c1.w, d1.w);
    }
}

// ---------------------------------------------------------------------------
// Launch: identify inputs by size (batch_size scalar / features / coords).
// ---------------------------------------------------------------------------
extern "C" void kernel_launch(void* const* d_in, const int* in_sizes, int n_in,
                              void* d_out, int out_size)
{
    // features is the largest input (P*128 floats); coords has P*4 ints.
    int fi = 0;
    long long best = -1;
    for (int i = 0; i < n_in; ++i) {
        if ((long long)in_sizes[i] > best) { best = in_sizes[i]; fi = i; }
    }
    const float* feat = (const float*)d_in[fi];
    int P = in_sizes[fi] / CH;

    const int* coords = nullptr;
    for (int i = 0; i < n_in; ++i) {
        if (i != fi && in_sizes[i] == P * 4) { coords = (const int*)d_in[i]; break; }
    }
    if (!coords) { // fallback: second-largest input
        int ci = -1; long long b2 = -1;
        for (int i = 0; i < n_in; ++i)
            if (i != fi && (long long)in_sizes[i] > b2) { b2 = in_sizes[i]; ci = i; }
        coords = (const int*)d_in[ci];
    }

    float* out = (float*)d_out;

    // Pass 0: reset index canvas to -1 (0xFF bytes). Memset node: capturable,
    // no allocation, ~1us for 4 MiB.
    void* idx_ptr = nullptr;
    cudaGetSymbolAddress(&idx_ptr, g_idx);
    cudaMemsetAsync(idx_ptr, 0xFF, TOTAL_CELLS * sizeof(int), 0);

    // Pass 1: scatter pillar indices
    build_idx_kernel<<<(P + 255) / 256, 256>>>(coords, P);

    // Pass 2: gather + transpose (4 threads per quad, 32 channels each)
    gather_kernel<<<(4 * NQUADS) / 256, 256>>>(feat, out);
}